// round 8
// baseline (speedup 1.0000x reference)
#include <cuda_runtime.h>
#include <cuda_fp16.h>
#include <cstdint>

#define T_STEPS 256
#define BATCH   16
#define HID     100
#define G4      400
#define VOCAB   30522
#define M_ROWS  4096   // T*B
#define KP      112    // K padded to 7 x 16

// Vocab GEMM tiling
#define MT    128              // m-tile rows
#define NT    192
#define NBLK  159              // ceil(VOCAB/192)
#define NPAD  (NBLK * NT)      // 30528
#define SEG_M 8                // m-tiles per stolen segment (8 x 128 = 1024 rows)
#define NSEG  (NBLK * 4)       // 636
#define ROWB  240              // smem row bytes (112 fp16 = 224, pad to 240)
#define ROWW  60

// gx GEMM tiling
#define GXM   128
#define GXN   224

// ---------------------------------------------------------------------------
// Device scratch
// ---------------------------------------------------------------------------
__device__ float g_gx[(size_t)M_ROWS * G4];
__device__ float g_hs[(size_t)M_ROWS * HID];
__device__ __align__(16) __half gA_hi[(size_t)M_ROWS * KP];
__device__ __align__(16) __half gA_lo[(size_t)M_ROWS * KP];
__device__ __align__(16) __half gW_hi[(size_t)NPAD * KP];   // vocab W: hi only
__device__ __align__(16) __half gE_hi[(size_t)M_ROWS * KP];
__device__ __align__(16) __half gE_lo[(size_t)M_ROWS * KP];
__device__ __align__(16) __half gWih_hi[(size_t)448 * KP];
__device__ __align__(16) __half gWih_lo[(size_t)448 * KP];
__device__ int g_counter;

// ---------------------------------------------------------------------------
// helpers
// ---------------------------------------------------------------------------
__device__ __forceinline__ uint32_t smem_u32(const void* p) {
    uint32_t a;
    asm("{ .reg .u64 t; cvta.to.shared.u64 t, %1; cvt.u32.u64 %0, t; }"
        : "=r"(a) : "l"(p));
    return a;
}
__device__ __forceinline__ void cp16(uint32_t dst, const void* src) {
    asm volatile("cp.async.ca.shared.global [%0], [%1], 16;" :: "r"(dst), "l"(src));
}
__device__ __forceinline__ void mma_fp16(float* c, const uint32_t* a,
                                         uint32_t b0, uint32_t b1) {
    asm volatile(
        "mma.sync.aligned.m16n8k16.row.col.f32.f16.f16.f32 "
        "{%0,%1,%2,%3},{%4,%5,%6,%7},{%8,%9},{%0,%1,%2,%3};\n"
        : "+f"(c[0]), "+f"(c[1]), "+f"(c[2]), "+f"(c[3])
        : "r"(a[0]), "r"(a[1]), "r"(a[2]), "r"(a[3]), "r"(b0), "r"(b1));
}
#define LDSM4(r, a) \
    asm volatile("ldmatrix.sync.aligned.m8n8.x4.shared.b16 {%0,%1,%2,%3}, [%4];" \
        : "=r"((r)[0]), "=r"((r)[1]), "=r"((r)[2]), "=r"((r)[3]) : "r"(a))
#define LDSM2(r, a) \
    asm volatile("ldmatrix.sync.aligned.m8n8.x2.shared.b16 {%0,%1}, [%2];" \
        : "=r"((r)[0]), "=r"((r)[1]) : "r"(a))

__device__ __forceinline__ void split8(const float* v, uint32_t* ph, uint32_t* pl) {
    #pragma unroll
    for (int j = 0; j < 4; j++) {
        __half h0 = __float2half_rn(v[2*j]);
        __half h1 = __float2half_rn(v[2*j+1]);
        __half l0 = __float2half_rn(v[2*j]   - __half2float(h0));
        __half l1 = __float2half_rn(v[2*j+1] - __half2float(h1));
        ph[j] = (uint32_t)__half_as_ushort(h0) | ((uint32_t)__half_as_ushort(h1) << 16);
        pl[j] = (uint32_t)__half_as_ushort(l0) | ((uint32_t)__half_as_ushort(l1) << 16);
    }
}

// ---------------------------------------------------------------------------
// Kernel 0: presplit (emb gather -> gE hi/lo; W_ih -> gWih; out_W -> gW hi)
// + reset work-steal counter.  (unchanged from R7)
// ---------------------------------------------------------------------------
#define U_E    (M_ROWS * 14)
#define U_WIH  (448 * 14)
#define U_W    (NPAD * 14)
#define U_TOT  (U_E + U_WIH + U_W)           // 491008 = 1918*256

__global__ __launch_bounds__(256) void presplit_kernel(
        const int* __restrict__ input, const float* __restrict__ emb,
        const float* __restrict__ dec_W_ih, const float* __restrict__ out_W) {
    if (blockIdx.x == 0 && threadIdx.x == 0) g_counter = 0;
    const int u = blockIdx.x * 256 + threadIdx.x;
    float v[8];
    uint32_t ph[4], pl[4];

    if (u < U_E) {
        int row = u / 14, k0 = (u % 14) * 8;
        const float* src = emb + (size_t)input[row] * HID;
        #pragma unroll
        for (int i = 0; i < 8; i++) {
            int k = k0 + i;
            v[i] = (k < HID) ? src[k] : 0.f;
        }
        split8(v, ph, pl);
        size_t d = (size_t)row * KP + k0;
        *(uint4*)(gE_hi + d) = make_uint4(ph[0], ph[1], ph[2], ph[3]);
        *(uint4*)(gE_lo + d) = make_uint4(pl[0], pl[1], pl[2], pl[3]);
    } else if (u < U_E + U_WIH) {
        int w = u - U_E;
        int row = w / 14, k0 = (w % 14) * 8;
        #pragma unroll
        for (int i = 0; i < 8; i++) {
            int k = k0 + i;
            v[i] = (row < G4 && k < HID) ? dec_W_ih[(size_t)row * HID + k] : 0.f;
        }
        split8(v, ph, pl);
        size_t d = (size_t)row * KP + k0;
        *(uint4*)(gWih_hi + d) = make_uint4(ph[0], ph[1], ph[2], ph[3]);
        *(uint4*)(gWih_lo + d) = make_uint4(pl[0], pl[1], pl[2], pl[3]);
    } else {
        int w = u - U_E - U_WIH;
        int row = w / 14, k0 = (w % 14) * 8;
        #pragma unroll
        for (int i = 0; i < 8; i++) {
            int k = k0 + i;
            v[i] = (row < VOCAB && k < HID) ? out_W[(size_t)row * HID + k] : 0.f;
        }
        #pragma unroll
        for (int j = 0; j < 4; j++) {
            __half h0 = __float2half_rn(v[2*j]);
            __half h1 = __float2half_rn(v[2*j+1]);
            ph[j] = (uint32_t)__half_as_ushort(h0) |
                    ((uint32_t)__half_as_ushort(h1) << 16);
        }
        *(uint4*)(gW_hi + (size_t)row * KP + k0) =
            make_uint4(ph[0], ph[1], ph[2], ph[3]);
    }
}

// ---------------------------------------------------------------------------
// Kernel 1: gx via HMMA (3-term split). Grid 64.  (unchanged from R7)
// ---------------------------------------------------------------------------
#define SMX_BIAS 0
#define SMX_A    1024
#define SMX_B    (SMX_A + 2 * GXM * ROWB)
#define SMX_TOT  (SMX_B + 2 * GXN * ROWB)    // 169984

__global__ __launch_bounds__(256, 1) void gx_mma_kernel(
        const float* __restrict__ b_ih, const float* __restrict__ b_hh) {
    extern __shared__ char sm[];
    const uint32_t sb = smem_u32(sm);
    const int tid = threadIdx.x;
    const int nblk = blockIdx.x & 1, mt = blockIdx.x >> 1;
    const int m0 = mt * GXM, n0 = nblk * GXN;

    for (int c = tid; c < GXN; c += 256) {
        int j = n0 + c;
        ((float*)(sm + SMX_BIAS))[c] = (j < G4) ? b_ih[j] + b_hh[j] : 0.f;
    }
    for (int e = tid; e < 3584; e += 256) {
        int arr = e >= 1792, r = (e - arr * 1792) / 14, c = e % 14;
        const __half* src = (arr ? gE_lo : gE_hi) + (size_t)(m0 + r) * KP + c * 8;
        cp16(sb + SMX_A + arr * 30720 + r * ROWB + c * 16, src);
    }
    for (int e = tid; e < 6272; e += 256) {
        int arr = e >= 3136, r = (e - arr * 3136) / 14, c = e % 14;
        const __half* src = (arr ? gWih_lo : gWih_hi) + (size_t)(n0 + r) * KP + c * 8;
        cp16(sb + SMX_B + arr * 53760 + r * ROWB + c * 16, src);
    }
    asm volatile("cp.async.commit_group;");
    asm volatile("cp.async.wait_group 0;");
    __syncthreads();

    const int wid = tid >> 5, lane = tid & 31;
    const int wm = wid >> 2, wn = wid & 3;
    const int gid = lane >> 2, tig = lane & 3;
    const uint32_t* A32 = (const uint32_t*)(sm + SMX_A);
    const uint32_t* B32 = (const uint32_t*)(sm + SMX_B);

    float acc[4][7][4];
    #pragma unroll
    for (int mb = 0; mb < 4; mb++)
        #pragma unroll
        for (int nb = 0; nb < 7; nb++)
            #pragma unroll
            for (int q = 0; q < 4; q++) acc[mb][nb][q] = 0.f;

    #pragma unroll 1
    for (int ks = 0; ks < 7; ks++) {
        uint32_t ah[4][4], al[4][4];
        #pragma unroll
        for (int mb = 0; mb < 4; mb++) {
            int w = (wm * 64 + mb * 16 + gid) * ROWW + ks * 8 + tig;
            ah[mb][0] = A32[w];            al[mb][0] = A32[w + 7680];
            ah[mb][1] = A32[w + 8 * ROWW]; al[mb][1] = A32[w + 7680 + 8 * ROWW];
            ah[mb][2] = A32[w + 4];        al[mb][2] = A32[w + 7680 + 4];
            ah[mb][3] = A32[w + 8 * ROWW + 4];
            al[mb][3] = A32[w + 7680 + 8 * ROWW + 4];
        }
        #pragma unroll
        for (int nb = 0; nb < 7; nb++) {
            int w = (wn * 56 + nb * 8 + gid) * ROWW + ks * 8 + tig;
            uint32_t bh0 = B32[w], bh1 = B32[w + 4];
            uint32_t bl0 = B32[w + 13440], bl1 = B32[w + 13440 + 4];
            #pragma unroll
            for (int mb = 0; mb < 4; mb++) {
                mma_fp16(acc[mb][nb], ah[mb], bh0, bh1);
                mma_fp16(acc[mb][nb], ah[mb], bl0, bl1);
                mma_fp16(acc[mb][nb], al[mb], bh0, bh1);
            }
        }
    }

    const float* biasS = (const float*)(sm + SMX_BIAS);
    #pragma unroll
    for (int nb = 0; nb < 7; nb++) {
        int jl = wn * 56 + nb * 8 + tig * 2;
        int j  = n0 + jl;
        if (j < G4) {
            float b0 = biasS[jl], b1 = biasS[jl + 1];
            #pragma unroll
            for (int mb = 0; mb < 4; mb++) {
                int row = m0 + wm * 64 + mb * 16 + gid;
                *(float2*)(g_gx + (size_t)row * G4 + j) =
                    make_float2(acc[mb][nb][0] + b0, acc[mb][nb][1] + b1);
                *(float2*)(g_gx + (size_t)(row + 8) * G4 + j) =
                    make_float2(acc[mb][nb][2] + b0, acc[mb][nb][3] + b1);
            }
        }
    }
}

// ---------------------------------------------------------------------------
// Kernel 2: LSTM recurrence — FROZEN at the R4/R7 configuration.
// ---------------------------------------------------------------------------
__device__ __forceinline__ void fma2(unsigned long long& acc,
                                     unsigned long long a,
                                     unsigned long long b) {
    asm("fma.rn.f32x2 %0, %1, %2, %0;" : "+l"(acc) : "l"(a), "l"(b));
}
__device__ __forceinline__ float unpack_sum(unsigned long long a) {
    float lo, hi;
    asm("mov.b64 {%0, %1}, %2;" : "=f"(lo), "=f"(hi) : "l"(a));
    return lo + hi;
}

__global__ __launch_bounds__(416, 1) void lstm_kernel(const float* __restrict__ W_hh) {
    __shared__ __align__(16) float h_s[HID];
    __shared__ float acts[G4];
    const int j = threadIdx.x;
    const int b = blockIdx.x;

    unsigned long long w2[50];
    if (j < G4) {
        const unsigned long long* wg =
            (const unsigned long long*)(W_hh + (size_t)j * HID);
        #pragma unroll
        for (int k = 0; k < 50; k++) w2[k] = wg[k];
    }
    if (j < HID) h_s[j] = 0.f;
    float c = 0.f;
    float gcur = (j < G4) ? g_gx[(size_t)b * G4 + j] : 0.f;
    __syncthreads();

    for (int t = 0; t < T_STEPS; t++) {
        float gnext = 0.f;
        if (t + 1 < T_STEPS && j < G4)
            gnext = g_gx[((size_t)(t + 1) * BATCH + b) * G4 + j];

        float a = 0.f;
        if (j < G4) {
            const unsigned long long* h2 = (const unsigned long long*)h_s;
            unsigned long long acc0 = 0ull, acc1 = 0ull;
            #pragma unroll
            for (int k = 0; k < 50; k += 2) {
                fma2(acc0, w2[k],     h2[k]);
                fma2(acc1, w2[k + 1], h2[k + 1]);
            }
            float d = gcur + unpack_sum(acc0) + unpack_sum(acc1);
            if (j >= 2 * HID && j < 3 * HID) a = tanhf(d);
            else                             a = 1.f / (1.f + expf(-d));
            acts[j] = a;
        }
        __syncthreads();

        if (j < HID) {
            float ig = acts[j], fg = acts[HID + j];
            float gg = acts[2 * HID + j], og = acts[3 * HID + j];
            c = fg * c + ig * gg;
            float hn = og * tanhf(c);
            h_s[j] = hn;
            g_hs[((size_t)t * BATCH + b) * HID + j] = hn;
        }
        __syncthreads();
        gcur = gnext;
    }
}

// ---------------------------------------------------------------------------
// Kernel 2.5: splitA — g_hs -> gA hi/lo fp16.  (unchanged)
// ---------------------------------------------------------------------------
#define A_UNITS (M_ROWS * 14)   // 57344 = 224*256

__global__ __launch_bounds__(256) void splitA_kernel() {
    const int u = blockIdx.x * 256 + threadIdx.x;
    int row = u / 14, k0 = (u % 14) * 8;
    float v[8];
    #pragma unroll
    for (int i = 0; i < 8; i++) {
        int k = k0 + i;
        v[i] = (k < HID) ? g_hs[(size_t)row * HID + k] : 0.f;
    }
    uint32_t ph[4], pl[4];
    split8(v, ph, pl);
    size_t d = (size_t)row * KP + k0;
    *(uint4*)(gA_hi + d) = make_uint4(ph[0], ph[1], ph[2], ph[3]);
    *(uint4*)(gA_lo + d) = make_uint4(pl[0], pl[1], pl[2], pl[3]);
}

// ---------------------------------------------------------------------------
// Kernel 3: vocab GEMM — 16 warps/SM. One 512-thread CTA per SM, 128x192
// tile, warps 2(M) x 8(N) -> warp tile 64x24. A hi/lo double-buffered via
// cp.async; B loaded once per 8-m-tile segment; work-stealing.
// ---------------------------------------------------------------------------
#define SMG_BIAS 0                      // 192 floats
#define SMG_SEG  768
#define SMG_A    1024
#define SMG_ABUF 61440                  // per buffer: hi 30720 + lo 30720
#define SMG_B    (SMG_A + 2 * SMG_ABUF) // 123904: hi only, 192x240 = 46080
#define SMG_TOT  (SMG_B + NT * ROWB)    // 169984

__global__ __launch_bounds__(512, 1) void gemm_kernel(
        const float* __restrict__ out_b, float* __restrict__ out) {
    extern __shared__ char sm[];
    const uint32_t sb = smem_u32(sm);
    const int tid = threadIdx.x;
    const int wid = tid >> 5, lane = tid & 31;
    const int wm = wid >> 3, wn = wid & 7;     // 2(M) x 8(N)
    const int gid = lane >> 2, tig = lane & 3;

    // ldmatrix lane addressing
    const uint32_t a_off = (uint32_t)(wm * 64 * ROWB +
                                      (lane & 15) * ROWB + (lane >> 4) * 16);
    const uint32_t b4_off = sb + SMG_B +
        (uint32_t)((wn * 24 + ((lane >> 4) & 1) * 8 + (lane & 7)) * ROWB +
                   ((lane >> 3) & 1) * 16);
    const uint32_t b2_off = sb + SMG_B +
        (uint32_t)((wn * 24 + 16 + (lane & 7)) * ROWB +
                   ((lane >> 3) & 1) * 16);

    for (;;) {
        if (tid == 0) *(int*)(sm + SMG_SEG) = atomicAdd(&g_counter, 1);
        __syncthreads();
        const int seg = *(const int*)(sm + SMG_SEG);
        if (seg >= NSEG) break;
        const int n0  = (seg >> 2) * NT;
        const int mt0 = (seg & 3) * SEG_M;     // m-tile index (128-row tiles)

        // bias + B (once per segment) + A tile 0
        if (tid < NT) {
            int col = n0 + tid;
            ((float*)(sm + SMG_BIAS))[tid] = (col < VOCAB) ? out_b[col] : 0.f;
        }
        for (int e = tid; e < 2688; e += 512) {
            int r = e / 14, c = e % 14;
            cp16(sb + SMG_B + r * ROWB + c * 16,
                 gW_hi + (size_t)(n0 + r) * KP + c * 8);
        }
        {
            const int m0 = mt0 * MT;
            for (int e = tid; e < 3584; e += 512) {
                int arr = e >= 1792, r = (e - arr * 1792) / 14, c = e % 14;
                cp16(sb + SMG_A + arr * 30720 + r * ROWB + c * 16,
                     (arr ? gA_lo : gA_hi) + (size_t)(m0 + r) * KP + c * 8);
            }
        }
        asm volatile("cp.async.commit_group;");

        #pragma unroll 1
        for (int it = 0; it < SEG_M; it++) {
            asm volatile("cp.async.wait_group 0;");
            __syncthreads();   // A_it ready; everyone done with the other buf

            if (it < SEG_M - 1) {   // prefetch A_{it+1} into the other buffer
                const int m1 = (mt0 + it + 1) * MT;
                const uint32_t abase = sb + SMG_A + ((it + 1) & 1) * SMG_ABUF;
                for (int e = tid; e < 3584; e += 512) {
                    int arr = e >= 1792, r = (e - arr * 1792) / 14, c = e % 14;
                    cp16(abase + arr * 30720 + r * ROWB + c * 16,
                         (arr ? gA_lo : gA_hi) + (size_t)(m1 + r) * KP + c * 8);
                }
                asm volatile("cp.async.commit_group;");
            }

            const uint32_t a_cur = sb + SMG_A + (it & 1) * SMG_ABUF + a_off;

            float acc[4][3][4];
            #pragma unroll
            for (int mb = 0; mb < 4; mb++)
                #pragma unroll
                for (int nb = 0; nb < 3; nb++)
                    #pragma unroll
                    for (int q = 0; q < 4; q++) acc[mb][nb][q] = 0.f;

            #pragma unroll
            for (int ks = 0; ks < 7; ks++) {
                uint32_t ah[4][4], al[4][4], bb4[4], bb2[2];
                #pragma unroll
                for (int mb = 0; mb < 4; mb++) {
                    LDSM4(ah[mb], a_cur + mb * 3840 + ks * 32);
                    LDSM4(al[mb], a_cur + 30720 + mb * 3840 + ks * 32);
                }
                LDSM4(bb4, b4_off + ks * 32);
                LDSM2(bb2, b2_off + ks * 32);

                #pragma unroll
                for (int mb = 0; mb < 4; mb++) {
                    mma_fp16(acc[mb][0], ah[mb], bb4[0], bb4[1]);
                    mma_fp16(acc[mb][0], al[mb], bb4[0], bb4[1]);
                    mma_fp16(acc[mb][1], ah[mb], bb4[2], bb4[3]);
                    mma_fp16(acc[mb][1], al[mb], bb4[2], bb4[3]);
                    mma_fp16(acc[mb][2], ah[mb], bb2[0], bb2[1]);
                    mma_fp16(acc[mb][2], al[mb], bb2[0], bb2[1]);
                }
            }

            // epilogue: direct float2 stores
            const int m0 = (mt0 + it) * MT;
            const float* biasS = (const float*)(sm + SMG_BIAS);
            #pragma unroll
            for (int nb = 0; nb < 3; nb++) {
                int cl  = wn * 24 + nb * 8 + tig * 2;
                int col = n0 + cl;
                if (col < VOCAB) {
                    float b0 = biasS[cl], b1 = biasS[cl + 1];
                    #pragma unroll
                    for (int mb = 0; mb < 4; mb++) {
                        int row = m0 + wm * 64 + mb * 16 + gid;
                        *(float2*)(out + (size_t)row * VOCAB + col) =
                            make_float2(acc[mb][nb][0] + b0, acc[mb][nb][1] + b1);
                        *(float2*)(out + (size_t)(row + 8) * VOCAB + col) =
                            make_float2(acc[mb][nb][2] + b0, acc[mb][nb][3] + b1);
                    }
                }
            }
        }
        __syncthreads();   // protect bias/B rewrite at next segment
    }
}

// ---------------------------------------------------------------------------
// Launch. Inputs: 0 input, 1 emb, 2..5 enc_* (dead), 6 dec_W_ih, 7 dec_W_hh,
// 8 dec_b_ih, 9 dec_b_hh, 10 out_W, 11 out_b.
// ---------------------------------------------------------------------------
extern "C" void kernel_launch(void* const* d_in, const int* in_sizes, int n_in,
                              void* d_out, int out_size) {
    (void)in_sizes; (void)n_in; (void)out_size;
    const int*   input = (const int*)d_in[0];
    const float* emb   = (const float*)d_in[1];
    const float* dWih  = (const float*)d_in[6];
    const float* dWhh  = (const float*)d_in[7];
    const float* dbih  = (const float*)d_in[8];
    const float* dbhh  = (const float*)d_in[9];
    const float* outW  = (const float*)d_in[10];
    const float* outb  = (const float*)d_in[11];
    float* out = (float*)d_out;

    cudaFuncSetAttribute(gx_mma_kernel,
                         cudaFuncAttributeMaxDynamicSharedMemorySize, SMX_TOT);
    cudaFuncSetAttribute(gemm_kernel,
                         cudaFuncAttributeMaxDynamicSharedMemorySize, SMG_TOT);

    presplit_kernel<<<U_TOT / 256, 256>>>(input, emb, dWih, outW);
    gx_mma_kernel<<<64, 256, SMX_TOT>>>(dbih, dbhh);
    lstm_kernel<<<BATCH, 416>>>(dWhh);
    splitA_kernel<<<A_UNITS / 256, 256>>>();
    gemm_kernel<<<148, 512, SMG_TOT>>>(outb, out);
}

// round 9
// speedup vs baseline: 1.1836x; 1.1836x over previous
#include <cuda_runtime.h>
#include <cuda_fp16.h>
#include <cstdint>

#define T_STEPS 256
#define BATCH   16
#define HID     100
#define G4      400
#define VOCAB   30522
#define M_ROWS  4096   // T*B
#define KP      112    // K padded to 7 x 16

// Vocab GEMM tiling (fused kernel)
#define MT    128
#define NT    192
#define NBLK  159               // ceil(VOCAB/192)
#define NPAD  (NBLK * NT)       // 30528
#define SEG_M 4                 // m-tiles per segment -> 512-row chunks
#define NCHK  8                 // 4096 / 512
#define NSEG  (NCHK * NBLK)     // 1272
#define ROWB  240               // smem row bytes (112 fp16 = 224, pad to 240)
#define ROWW  60

// gx GEMM tiling
#define GXM   128
#define GXN   224

// ---------------------------------------------------------------------------
// Device scratch
// ---------------------------------------------------------------------------
__device__ float g_gx[(size_t)M_ROWS * G4];
__device__ __align__(16) __half gA_hi[(size_t)M_ROWS * KP];
__device__ __align__(16) __half gA_lo[(size_t)M_ROWS * KP];
__device__ __align__(16) __half gW_hi[(size_t)NPAD * KP];   // vocab W: hi only
__device__ __align__(16) __half gE_hi[(size_t)M_ROWS * KP];
__device__ __align__(16) __half gE_lo[(size_t)M_ROWS * KP];
__device__ __align__(16) __half gWih_hi[(size_t)448 * KP];
__device__ __align__(16) __half gWih_lo[(size_t)448 * KP];
__device__ int g_counter;
__device__ int g_prog[BATCH];    // lstm steps published, per batch element

// ---------------------------------------------------------------------------
// helpers
// ---------------------------------------------------------------------------
__device__ __forceinline__ uint32_t smem_u32(const void* p) {
    uint32_t a;
    asm("{ .reg .u64 t; cvta.to.shared.u64 t, %1; cvt.u32.u64 %0, t; }"
        : "=r"(a) : "l"(p));
    return a;
}
__device__ __forceinline__ void cp16(uint32_t dst, const void* src) {
    asm volatile("cp.async.ca.shared.global [%0], [%1], 16;" :: "r"(dst), "l"(src));
}
__device__ __forceinline__ void mma_fp16(float* c, const uint32_t* a,
                                         uint32_t b0, uint32_t b1) {
    asm volatile(
        "mma.sync.aligned.m16n8k16.row.col.f32.f16.f16.f32 "
        "{%0,%1,%2,%3},{%4,%5,%6,%7},{%8,%9},{%0,%1,%2,%3};\n"
        : "+f"(c[0]), "+f"(c[1]), "+f"(c[2]), "+f"(c[3])
        : "r"(a[0]), "r"(a[1]), "r"(a[2]), "r"(a[3]), "r"(b0), "r"(b1));
}
#define LDSM4(r, a) \
    asm volatile("ldmatrix.sync.aligned.m8n8.x4.shared.b16 {%0,%1,%2,%3}, [%4];" \
        : "=r"((r)[0]), "=r"((r)[1]), "=r"((r)[2]), "=r"((r)[3]) : "r"(a))

__device__ __forceinline__ void split8(const float* v, uint32_t* ph, uint32_t* pl) {
    #pragma unroll
    for (int j = 0; j < 4; j++) {
        __half h0 = __float2half_rn(v[2*j]);
        __half h1 = __float2half_rn(v[2*j+1]);
        __half l0 = __float2half_rn(v[2*j]   - __half2float(h0));
        __half l1 = __float2half_rn(v[2*j+1] - __half2float(h1));
        ph[j] = (uint32_t)__half_as_ushort(h0) | ((uint32_t)__half_as_ushort(h1) << 16);
        pl[j] = (uint32_t)__half_as_ushort(l0) | ((uint32_t)__half_as_ushort(l1) << 16);
    }
}
__device__ __forceinline__ float sigf(float x) {
    return 1.f / (1.f + __expf(-x));
}
__device__ __forceinline__ float tanh_fast(float x) {
    return 2.f / (1.f + __expf(-2.f * x)) - 1.f;
}
__device__ __forceinline__ int ld_acq(const int* p) {
    int v;
    asm volatile("ld.acquire.gpu.global.b32 %0, [%1];" : "=r"(v) : "l"(p) : "memory");
    return v;
}
__device__ __forceinline__ void st_rel(int* p, int v) {
    asm volatile("st.release.gpu.global.b32 [%0], %1;" :: "l"(p), "r"(v) : "memory");
}

// ---------------------------------------------------------------------------
// Kernel 0: presplit + reset counter/progress.
// ---------------------------------------------------------------------------
#define U_E    (M_ROWS * 14)
#define U_WIH  (448 * 14)
#define U_W    (NPAD * 14)
#define U_TOT  (U_E + U_WIH + U_W)           // 491008 = 1918*256

__global__ __launch_bounds__(256) void presplit_kernel(
        const int* __restrict__ input, const float* __restrict__ emb,
        const float* __restrict__ dec_W_ih, const float* __restrict__ out_W) {
    if (blockIdx.x == 0) {
        if (threadIdx.x < BATCH) g_prog[threadIdx.x] = 0;
        if (threadIdx.x == BATCH) g_counter = 0;
    }
    const int u = blockIdx.x * 256 + threadIdx.x;
    float v[8];
    uint32_t ph[4], pl[4];

    if (u < U_E) {
        int row = u / 14, k0 = (u % 14) * 8;
        const float* src = emb + (size_t)input[row] * HID;
        #pragma unroll
        for (int i = 0; i < 8; i++) {
            int k = k0 + i;
            v[i] = (k < HID) ? src[k] : 0.f;
        }
        split8(v, ph, pl);
        size_t d = (size_t)row * KP + k0;
        *(uint4*)(gE_hi + d) = make_uint4(ph[0], ph[1], ph[2], ph[3]);
        *(uint4*)(gE_lo + d) = make_uint4(pl[0], pl[1], pl[2], pl[3]);
    } else if (u < U_E + U_WIH) {
        int w = u - U_E;
        int row = w / 14, k0 = (w % 14) * 8;
        #pragma unroll
        for (int i = 0; i < 8; i++) {
            int k = k0 + i;
            v[i] = (row < G4 && k < HID) ? dec_W_ih[(size_t)row * HID + k] : 0.f;
        }
        split8(v, ph, pl);
        size_t d = (size_t)row * KP + k0;
        *(uint4*)(gWih_hi + d) = make_uint4(ph[0], ph[1], ph[2], ph[3]);
        *(uint4*)(gWih_lo + d) = make_uint4(pl[0], pl[1], pl[2], pl[3]);
    } else {
        int w = u - U_E - U_WIH;
        int row = w / 14, k0 = (w % 14) * 8;
        #pragma unroll
        for (int i = 0; i < 8; i++) {
            int k = k0 + i;
            v[i] = (row < VOCAB && k < HID) ? out_W[(size_t)row * HID + k] : 0.f;
        }
        #pragma unroll
        for (int j = 0; j < 4; j++) {
            __half h0 = __float2half_rn(v[2*j]);
            __half h1 = __float2half_rn(v[2*j+1]);
            ph[j] = (uint32_t)__half_as_ushort(h0) |
                    ((uint32_t)__half_as_ushort(h1) << 16);
        }
        *(uint4*)(gW_hi + (size_t)row * KP + k0) =
            make_uint4(ph[0], ph[1], ph[2], ph[3]);
    }
}

// ---------------------------------------------------------------------------
// Kernel 1: gx via HMMA (3-term split). Grid 64.  (unchanged)
// ---------------------------------------------------------------------------
#define SMX_BIAS 0
#define SMX_A    1024
#define SMX_B    (SMX_A + 2 * GXM * ROWB)
#define SMX_TOT  (SMX_B + 2 * GXN * ROWB)    // 169984

__global__ __launch_bounds__(256, 1) void gx_mma_kernel(
        const float* __restrict__ b_ih, const float* __restrict__ b_hh) {
    extern __shared__ char sm[];
    const uint32_t sb = smem_u32(sm);
    const int tid = threadIdx.x;
    const int nblk = blockIdx.x & 1, mt = blockIdx.x >> 1;
    const int m0 = mt * GXM, n0 = nblk * GXN;

    for (int c = tid; c < GXN; c += 256) {
        int j = n0 + c;
        ((float*)(sm + SMX_BIAS))[c] = (j < G4) ? b_ih[j] + b_hh[j] : 0.f;
    }
    for (int e = tid; e < 3584; e += 256) {
        int arr = e >= 1792, r = (e - arr * 1792) / 14, c = e % 14;
        const __half* src = (arr ? gE_lo : gE_hi) + (size_t)(m0 + r) * KP + c * 8;
        cp16(sb + SMX_A + arr * 30720 + r * ROWB + c * 16, src);
    }
    for (int e = tid; e < 6272; e += 256) {
        int arr = e >= 3136, r = (e - arr * 3136) / 14, c = e % 14;
        const __half* src = (arr ? gWih_lo : gWih_hi) + (size_t)(n0 + r) * KP + c * 8;
        cp16(sb + SMX_B + arr * 53760 + r * ROWB + c * 16, src);
    }
    asm volatile("cp.async.commit_group;");
    asm volatile("cp.async.wait_group 0;");
    __syncthreads();

    const int wid = tid >> 5, lane = tid & 31;
    const int wm = wid >> 2, wn = wid & 3;
    const int gid = lane >> 2, tig = lane & 3;
    const uint32_t* A32 = (const uint32_t*)(sm + SMX_A);
    const uint32_t* B32 = (const uint32_t*)(sm + SMX_B);

    float acc[4][7][4];
    #pragma unroll
    for (int mb = 0; mb < 4; mb++)
        #pragma unroll
        for (int nb = 0; nb < 7; nb++)
            #pragma unroll
            for (int q = 0; q < 4; q++) acc[mb][nb][q] = 0.f;

    #pragma unroll 1
    for (int ks = 0; ks < 7; ks++) {
        uint32_t ah[4][4], al[4][4];
        #pragma unroll
        for (int mb = 0; mb < 4; mb++) {
            int w = (wm * 64 + mb * 16 + gid) * ROWW + ks * 8 + tig;
            ah[mb][0] = A32[w];            al[mb][0] = A32[w + 7680];
            ah[mb][1] = A32[w + 8 * ROWW]; al[mb][1] = A32[w + 7680 + 8 * ROWW];
            ah[mb][2] = A32[w + 4];        al[mb][2] = A32[w + 7680 + 4];
            ah[mb][3] = A32[w + 8 * ROWW + 4];
            al[mb][3] = A32[w + 7680 + 8 * ROWW + 4];
        }
        #pragma unroll
        for (int nb = 0; nb < 7; nb++) {
            int w = (wn * 56 + nb * 8 + gid) * ROWW + ks * 8 + tig;
            uint32_t bh0 = B32[w], bh1 = B32[w + 4];
            uint32_t bl0 = B32[w + 13440], bl1 = B32[w + 13440 + 4];
            #pragma unroll
            for (int mb = 0; mb < 4; mb++) {
                mma_fp16(acc[mb][nb], ah[mb], bh0, bh1);
                mma_fp16(acc[mb][nb], ah[mb], bl0, bl1);
                mma_fp16(acc[mb][nb], al[mb], bh0, bh1);
            }
        }
    }

    const float* biasS = (const float*)(sm + SMX_BIAS);
    #pragma unroll
    for (int nb = 0; nb < 7; nb++) {
        int jl = wn * 56 + nb * 8 + tig * 2;
        int j  = n0 + jl;
        if (j < G4) {
            float b0 = biasS[jl], b1 = biasS[jl + 1];
            #pragma unroll
            for (int mb = 0; mb < 4; mb++) {
                int row = m0 + wm * 64 + mb * 16 + gid;
                *(float2*)(g_gx + (size_t)row * G4 + j) =
                    make_float2(acc[mb][nb][0] + b0, acc[mb][nb][1] + b1);
                *(float2*)(g_gx + (size_t)(row + 8) * G4 + j) =
                    make_float2(acc[mb][nb][2] + b0, acc[mb][nb][3] + b1);
            }
        }
    }
}

// ---------------------------------------------------------------------------
// Kernel 2 (FUSED): blocks 0..15 = LSTM (publishes split-fp16 A every 8
// steps); blocks 16..147 = persistent GEMM consuming chunks in t-order.
// LSTM blocks fall through into the GEMM when their recurrence finishes.
// ---------------------------------------------------------------------------
#define FS_BIAS 0                      // 192 floats
#define FS_SEG  768
#define FS_A    1024
#define FS_ABUF 61440                  // per buffer: hi 30720 + lo 30720
#define FS_B    (FS_A + 2 * FS_ABUF)   // 123904 (hi only, 192*240 = 46080)
#define FS_TOT  (FS_B + NT * ROWB)     // 169984
// LSTM smem layout (same buffer, disjoint use): h_s@0, acts@512, h_hist@2176

__device__ __forceinline__ void poll_need(char* sm, int need) {
    if (threadIdx.x == 0) {
        for (;;) {
            int mn = 0x7fffffff;
            #pragma unroll
            for (int q = 0; q < BATCH; q++) mn = min(mn, ld_acq(&g_prog[q]));
            if (mn >= need) break;
            __nanosleep(256);
        }
    }
    __syncthreads();
}

__global__ __launch_bounds__(416, 1) void fused_kernel(
        const float* __restrict__ W_hh,
        const float* __restrict__ out_b,
        float* __restrict__ out) {
    extern __shared__ char sm[];
    const uint32_t sb = smem_u32(sm);
    const int tid = threadIdx.x;

    if (blockIdx.x < BATCH) {
        // ===================== LSTM producer =====================
        float* h_s    = (float*)sm;            // 100 floats
        float* acts   = (float*)(sm + 512);    // 400 floats
        float* h_hist = (float*)(sm + 2176);   // 8 x 112 floats
        const int j = tid;
        const int b = blockIdx.x;

        unsigned long long w2[50];
        if (j < G4) {
            const unsigned long long* wg =
                (const unsigned long long*)(W_hh + (size_t)j * HID);
            #pragma unroll
            for (int k = 0; k < 50; k++) w2[k] = wg[k];
        }
        if (j < HID) h_s[j] = 0.f;
        float c = 0.f;
        float gcur = (j < G4) ? g_gx[(size_t)b * G4 + j] : 0.f;
        __syncthreads();

        for (int t = 0; t < T_STEPS; t++) {
            float gnext = 0.f;
            if (t + 1 < T_STEPS && j < G4)
                gnext = g_gx[((size_t)(t + 1) * BATCH + b) * G4 + j];

            float a = 0.f;
            if (j < G4) {
                const unsigned long long* h2 = (const unsigned long long*)h_s;
                unsigned long long acc0, acc1;
                asm("mov.b64 %0, {%1, %1};" : "=l"(acc0) : "r"(0));
                asm("mov.b64 %0, {%1, %1};" : "=l"(acc1) : "r"(0));
                #pragma unroll
                for (int k = 0; k < 50; k += 2) {
                    asm("fma.rn.f32x2 %0, %1, %2, %0;"
                        : "+l"(acc0) : "l"(w2[k]), "l"(h2[k]));
                    asm("fma.rn.f32x2 %0, %1, %2, %0;"
                        : "+l"(acc1) : "l"(w2[k + 1]), "l"(h2[k + 1]));
                }
                float s0lo, s0hi, s1lo, s1hi;
                asm("mov.b64 {%0, %1}, %2;" : "=f"(s0lo), "=f"(s0hi) : "l"(acc0));
                asm("mov.b64 {%0, %1}, %2;" : "=f"(s1lo), "=f"(s1hi) : "l"(acc1));
                float d = gcur + (s0lo + s0hi) + (s1lo + s1hi);
                if (j >= 2 * HID && j < 3 * HID) a = tanh_fast(d);
                else                             a = sigf(d);
                acts[j] = a;
            }
            __syncthreads();

            if (j < HID) {
                float ig = acts[j], fg = acts[HID + j];
                float gg = acts[2 * HID + j], og = acts[3 * HID + j];
                c = fg * c + ig * gg;
                float hn = og * tanh_fast(c);
                h_s[j] = hn;
                h_hist[(t & 7) * KP + j] = hn;
            }
            __syncthreads();

            if ((t & 7) == 7) {
                // flush 8 rows as coalesced split-fp16 (224 units of 8 k)
                if (tid < 224) {
                    int row = tid / 28, rem = tid % 28;
                    int arr = rem / 14, cc = rem % 14;
                    size_t grow = (size_t)(t - 7 + row) * BATCH + b;
                    float v[8];
                    #pragma unroll
                    for (int i = 0; i < 8; i++) {
                        int k = cc * 8 + i;
                        v[i] = (k < HID) ? h_hist[row * KP + k] : 0.f;
                    }
                    uint32_t ph[4], pl[4];
                    split8(v, ph, pl);
                    __half* dst = (arr ? gA_lo : gA_hi) + grow * KP + cc * 8;
                    if (arr) *(uint4*)dst = make_uint4(pl[0], pl[1], pl[2], pl[3]);
                    else     *(uint4*)dst = make_uint4(ph[0], ph[1], ph[2], ph[3]);
                }
                __syncthreads();                  // flush stores done (CTA order)
                if (tid == 0) st_rel(&g_prog[b], t + 1);   // release to gpu scope
            }
            gcur = gnext;
        }
        __syncthreads();
        // fall through: help the GEMM with remaining segments
    }

    // ===================== GEMM consumer =====================
    const int wid = tid >> 5, lane = tid & 31;
    const int wm = (wid < 12) ? (wid / 6) : 0;     // 2(M) x 6(N), warps 0..11
    const int wn = (wid < 12) ? (wid % 6) : 0;
    const int gid = lane >> 2, tig = lane & 3;

    const uint32_t a_off = (uint32_t)(wm * 64 * ROWB +
                                      (lane & 15) * ROWB + (lane >> 4) * 16);
    const uint32_t b_base = sb + FS_B +
        (uint32_t)((wn * 32 + ((lane >> 4) & 1) * 8 + (lane & 7)) * ROWB +
                   ((lane >> 3) & 1) * 16);

    for (;;) {
        if (tid == 0) *(int*)(sm + FS_SEG) = atomicAdd(&g_counter, 1);
        __syncthreads();
        const int seg = *(const int*)(sm + FS_SEG);
        if (seg >= NSEG) break;
        const int mch  = seg / NBLK;          // chunk index (t-ordered)
        const int nblk = seg - mch * NBLK;
        const int n0   = nblk * NT;
        const int mt0  = mch * SEG_M;

        // bias + B (do not depend on LSTM progress)
        if (tid < NT) {
            int col = n0 + tid;
            ((float*)(sm + FS_BIAS))[tid] = (col < VOCAB) ? out_b[col] : 0.f;
        }
        for (int e = tid; e < 2688; e += 416) {
            int r = e / 14, cc = e % 14;
            cp16(sb + FS_B + r * ROWB + cc * 16,
                 gW_hi + (size_t)(n0 + r) * KP + cc * 8);
        }
        // wait for tile 0 rows, then load A0
        poll_need(sm, (mt0 + 1) * 8);
        {
            const int m0 = mt0 * MT;
            for (int e = tid; e < 3584; e += 416) {
                int arr = e >= 1792, r = (e - arr * 1792) / 14, cc = e % 14;
                cp16(sb + FS_A + arr * 30720 + r * ROWB + cc * 16,
                     (arr ? gA_lo : gA_hi) + (size_t)(m0 + r) * KP + cc * 8);
            }
        }
        asm volatile("cp.async.commit_group;");
        asm volatile("cp.async.wait_group 0;");
        __syncthreads();

        #pragma unroll 1
        for (int it = 0; it < SEG_M; it++) {
            if (it < SEG_M - 1) {   // gate + prefetch next A tile
                poll_need(sm, (mt0 + it + 2) * 8);
                const int m1 = (mt0 + it + 1) * MT;
                const uint32_t abase = sb + FS_A + ((it + 1) & 1) * FS_ABUF;
                for (int e = tid; e < 3584; e += 416) {
                    int arr = e >= 1792, r = (e - arr * 1792) / 14, cc = e % 14;
                    cp16(abase + arr * 30720 + r * ROWB + cc * 16,
                         (arr ? gA_lo : gA_hi) + (size_t)(m1 + r) * KP + cc * 8);
                }
                asm volatile("cp.async.commit_group;");
            }

            if (wid < 12) {
                const uint32_t a_cur = sb + FS_A + (it & 1) * FS_ABUF + a_off;

                float acc[4][4][4];
                #pragma unroll
                for (int mb = 0; mb < 4; mb++)
                    #pragma unroll
                    for (int nb = 0; nb < 4; nb++)
                        #pragma unroll
                        for (int q = 0; q < 4; q++) acc[mb][nb][q] = 0.f;

                #pragma unroll
                for (int ks = 0; ks < 7; ks++) {
                    uint32_t ah[4][4], al[4][4], bb[2][4];
                    #pragma unroll
                    for (int mb = 0; mb < 4; mb++) {
                        LDSM4(ah[mb], a_cur + mb * 3840 + ks * 32);
                        LDSM4(al[mb], a_cur + 30720 + mb * 3840 + ks * 32);
                    }
                    #pragma unroll
                    for (int p = 0; p < 2; p++)
                        LDSM4(bb[p], b_base + p * 3840 + ks * 32);

                    #pragma unroll
                    for (int p = 0; p < 2; p++) {
                        #pragma unroll
                        for (int mb = 0; mb < 4; mb++) {
                            mma_fp16(acc[mb][2*p],   ah[mb], bb[p][0], bb[p][1]);
                            mma_fp16(acc[mb][2*p],   al[mb], bb[p][0], bb[p][1]);
                            mma_fp16(acc[mb][2*p+1], ah[mb], bb[p][2], bb[p][3]);
                            mma_fp16(acc[mb][2*p+1], al[mb], bb[p][2], bb[p][3]);
                        }
                    }
                }

                const int m0 = (mt0 + it) * MT;
                const float* biasS = (const float*)(sm + FS_BIAS);
                #pragma unroll
                for (int nb = 0; nb < 4; nb++) {
                    int cl  = wn * 32 + nb * 8 + tig * 2;
                    int col = n0 + cl;
                    if (col < VOCAB) {
                        float b0 = biasS[cl], b1 = biasS[cl + 1];
                        #pragma unroll
                        for (int mb = 0; mb < 4; mb++) {
                            int row = m0 + wm * 64 + mb * 16 + gid;
                            *(float2*)(out + (size_t)row * VOCAB + col) =
                                make_float2(acc[mb][nb][0] + b0,
                                            acc[mb][nb][1] + b1);
                            *(float2*)(out + (size_t)(row + 8) * VOCAB + col) =
                                make_float2(acc[mb][nb][2] + b0,
                                            acc[mb][nb][3] + b1);
                        }
                    }
                }
            }

            if (it < SEG_M - 1) asm volatile("cp.async.wait_group 0;");
            __syncthreads();
        }
    }
}

// ---------------------------------------------------------------------------
// Launch. Inputs: 0 input, 1 emb, 2..5 enc_* (dead), 6 dec_W_ih, 7 dec_W_hh,
// 8 dec_b_ih, 9 dec_b_hh, 10 out_W, 11 out_b.
// ---------------------------------------------------------------------------
extern "C" void kernel_launch(void* const* d_in, const int* in_sizes, int n_in,
                              void* d_out, int out_size) {
    (void)in_sizes; (void)n_in; (void)out_size;
    const int*   input = (const int*)d_in[0];
    const float* emb   = (const float*)d_in[1];
    const float* dWih  = (const float*)d_in[6];
    const float* dWhh  = (const float*)d_in[7];
    const float* dbih  = (const float*)d_in[8];
    const float* dbhh  = (const float*)d_in[9];
    const float* outW  = (const float*)d_in[10];
    const float* outb  = (const float*)d_in[11];
    float* out = (float*)d_out;

    cudaFuncSetAttribute(gx_mma_kernel,
                         cudaFuncAttributeMaxDynamicSharedMemorySize, SMX_TOT);
    cudaFuncSetAttribute(fused_kernel,
                         cudaFuncAttributeMaxDynamicSharedMemorySize, FS_TOT);

    presplit_kernel<<<U_TOT / 256, 256>>>(input, emb, dWih, outW);
    gx_mma_kernel<<<64, 256, SMX_TOT>>>(dbih, dbhh);
    fused_kernel<<<148, 416, FS_TOT>>>(dWhh, outb, out);
}

// round 10
// speedup vs baseline: 1.2069x; 1.0197x over previous
#include <cuda_runtime.h>
#include <cuda_fp16.h>
#include <cstdint>

#define T_STEPS 256
#define BATCH   16
#define HID     100
#define G4      400
#define VOCAB   30522
#define M_ROWS  4096   // T*B
#define KP      112    // K padded to 7 x 16

// Vocab GEMM tiling (fused kernel)
#define MT    128
#define NT    192
#define NBLK  159               // ceil(VOCAB/192)
#define NPAD  (NBLK * NT)       // 30528
#define SEG_M 4                 // m-tiles per segment -> 512-row chunks
#define NCHK  8                 // 4096 / 512
#define NSEG  (NCHK * NBLK)     // 1272
#define ROWB  240               // smem row bytes (112 fp16 = 224, pad to 240)
#define ROWW  60

// gx GEMM tiling
#define GXM   128
#define GXN   224

// ---------------------------------------------------------------------------
// Device scratch
// ---------------------------------------------------------------------------
__device__ float g_gx[(size_t)M_ROWS * G4];
__device__ __align__(16) __half gA_hi[(size_t)M_ROWS * KP];   // A: fp16 hi ONLY
__device__ __align__(16) __half gW_hi[(size_t)NPAD * KP];     // vocab W: hi only
__device__ __align__(16) __half gE_hi[(size_t)M_ROWS * KP];
__device__ __align__(16) __half gE_lo[(size_t)M_ROWS * KP];
__device__ __align__(16) __half gWih_hi[(size_t)448 * KP];
__device__ __align__(16) __half gWih_lo[(size_t)448 * KP];
__device__ int g_counter;
__device__ int g_prog[BATCH];    // lstm steps published, per batch element

// ---------------------------------------------------------------------------
// helpers
// ---------------------------------------------------------------------------
__device__ __forceinline__ uint32_t smem_u32(const void* p) {
    uint32_t a;
    asm("{ .reg .u64 t; cvta.to.shared.u64 t, %1; cvt.u32.u64 %0, t; }"
        : "=r"(a) : "l"(p));
    return a;
}
__device__ __forceinline__ void cp16(uint32_t dst, const void* src) {
    asm volatile("cp.async.ca.shared.global [%0], [%1], 16;" :: "r"(dst), "l"(src));
}
__device__ __forceinline__ void mma_fp16(float* c, const uint32_t* a,
                                         uint32_t b0, uint32_t b1) {
    asm volatile(
        "mma.sync.aligned.m16n8k16.row.col.f32.f16.f16.f32 "
        "{%0,%1,%2,%3},{%4,%5,%6,%7},{%8,%9},{%0,%1,%2,%3};\n"
        : "+f"(c[0]), "+f"(c[1]), "+f"(c[2]), "+f"(c[3])
        : "r"(a[0]), "r"(a[1]), "r"(a[2]), "r"(a[3]), "r"(b0), "r"(b1));
}
#define LDSM4(r, a) \
    asm volatile("ldmatrix.sync.aligned.m8n8.x4.shared.b16 {%0,%1,%2,%3}, [%4];" \
        : "=r"((r)[0]), "=r"((r)[1]), "=r"((r)[2]), "=r"((r)[3]) : "r"(a))

__device__ __forceinline__ void split8(const float* v, uint32_t* ph, uint32_t* pl) {
    #pragma unroll
    for (int j = 0; j < 4; j++) {
        __half h0 = __float2half_rn(v[2*j]);
        __half h1 = __float2half_rn(v[2*j+1]);
        __half l0 = __float2half_rn(v[2*j]   - __half2float(h0));
        __half l1 = __float2half_rn(v[2*j+1] - __half2float(h1));
        ph[j] = (uint32_t)__half_as_ushort(h0) | ((uint32_t)__half_as_ushort(h1) << 16);
        pl[j] = (uint32_t)__half_as_ushort(l0) | ((uint32_t)__half_as_ushort(l1) << 16);
    }
}
__device__ __forceinline__ void pack8(const float* v, uint32_t* ph) {
    #pragma unroll
    for (int j = 0; j < 4; j++) {
        __half h0 = __float2half_rn(v[2*j]);
        __half h1 = __float2half_rn(v[2*j+1]);
        ph[j] = (uint32_t)__half_as_ushort(h0) | ((uint32_t)__half_as_ushort(h1) << 16);
    }
}
__device__ __forceinline__ float sigf(float x) {
    return 1.f / (1.f + __expf(-x));
}
__device__ __forceinline__ float tanh_fast(float x) {
    return 2.f / (1.f + __expf(-2.f * x)) - 1.f;
}
__device__ __forceinline__ int ld_acq(const int* p) {
    int v;
    asm volatile("ld.acquire.gpu.global.b32 %0, [%1];" : "=r"(v) : "l"(p) : "memory");
    return v;
}
__device__ __forceinline__ void st_rel(int* p, int v) {
    asm volatile("st.release.gpu.global.b32 [%0], %1;" :: "l"(p), "r"(v) : "memory");
}

// ---------------------------------------------------------------------------
// Kernel 0: presplit + reset counter/progress.
// ---------------------------------------------------------------------------
#define U_E    (M_ROWS * 14)
#define U_WIH  (448 * 14)
#define U_W    (NPAD * 14)
#define U_TOT  (U_E + U_WIH + U_W)           // 491008 = 1918*256

__global__ __launch_bounds__(256) void presplit_kernel(
        const int* __restrict__ input, const float* __restrict__ emb,
        const float* __restrict__ dec_W_ih, const float* __restrict__ out_W) {
    if (blockIdx.x == 0) {
        if (threadIdx.x < BATCH) g_prog[threadIdx.x] = 0;
        if (threadIdx.x == BATCH) g_counter = 0;
    }
    const int u = blockIdx.x * 256 + threadIdx.x;
    float v[8];
    uint32_t ph[4], pl[4];

    if (u < U_E) {
        int row = u / 14, k0 = (u % 14) * 8;
        const float* src = emb + (size_t)input[row] * HID;
        #pragma unroll
        for (int i = 0; i < 8; i++) {
            int k = k0 + i;
            v[i] = (k < HID) ? src[k] : 0.f;
        }
        split8(v, ph, pl);
        size_t d = (size_t)row * KP + k0;
        *(uint4*)(gE_hi + d) = make_uint4(ph[0], ph[1], ph[2], ph[3]);
        *(uint4*)(gE_lo + d) = make_uint4(pl[0], pl[1], pl[2], pl[3]);
    } else if (u < U_E + U_WIH) {
        int w = u - U_E;
        int row = w / 14, k0 = (w % 14) * 8;
        #pragma unroll
        for (int i = 0; i < 8; i++) {
            int k = k0 + i;
            v[i] = (row < G4 && k < HID) ? dec_W_ih[(size_t)row * HID + k] : 0.f;
        }
        split8(v, ph, pl);
        size_t d = (size_t)row * KP + k0;
        *(uint4*)(gWih_hi + d) = make_uint4(ph[0], ph[1], ph[2], ph[3]);
        *(uint4*)(gWih_lo + d) = make_uint4(pl[0], pl[1], pl[2], pl[3]);
    } else {
        int w = u - U_E - U_WIH;
        int row = w / 14, k0 = (w % 14) * 8;
        #pragma unroll
        for (int i = 0; i < 8; i++) {
            int k = k0 + i;
            v[i] = (row < VOCAB && k < HID) ? out_W[(size_t)row * HID + k] : 0.f;
        }
        pack8(v, ph);
        *(uint4*)(gW_hi + (size_t)row * KP + k0) =
            make_uint4(ph[0], ph[1], ph[2], ph[3]);
    }
}

// ---------------------------------------------------------------------------
// Kernel 1: gx via HMMA (3-term split, precision load-bearing). Grid 64.
// ---------------------------------------------------------------------------
#define SMX_BIAS 0
#define SMX_A    1024
#define SMX_B    (SMX_A + 2 * GXM * ROWB)
#define SMX_TOT  (SMX_B + 2 * GXN * ROWB)    // 169984

__global__ __launch_bounds__(256, 1) void gx_mma_kernel(
        const float* __restrict__ b_ih, const float* __restrict__ b_hh) {
    extern __shared__ char sm[];
    const uint32_t sb = smem_u32(sm);
    const int tid = threadIdx.x;
    const int nblk = blockIdx.x & 1, mt = blockIdx.x >> 1;
    const int m0 = mt * GXM, n0 = nblk * GXN;

    for (int c = tid; c < GXN; c += 256) {
        int j = n0 + c;
        ((float*)(sm + SMX_BIAS))[c] = (j < G4) ? b_ih[j] + b_hh[j] : 0.f;
    }
    for (int e = tid; e < 3584; e += 256) {
        int arr = e >= 1792, r = (e - arr * 1792) / 14, c = e % 14;
        const __half* src = (arr ? gE_lo : gE_hi) + (size_t)(m0 + r) * KP + c * 8;
        cp16(sb + SMX_A + arr * 30720 + r * ROWB + c * 16, src);
    }
    for (int e = tid; e < 6272; e += 256) {
        int arr = e >= 3136, r = (e - arr * 3136) / 14, c = e % 14;
        const __half* src = (arr ? gWih_lo : gWih_hi) + (size_t)(n0 + r) * KP + c * 8;
        cp16(sb + SMX_B + arr * 53760 + r * ROWB + c * 16, src);
    }
    asm volatile("cp.async.commit_group;");
    asm volatile("cp.async.wait_group 0;");
    __syncthreads();

    const int wid = tid >> 5, lane = tid & 31;
    const int wm = wid >> 2, wn = wid & 3;
    const int gid = lane >> 2, tig = lane & 3;
    const uint32_t* A32 = (const uint32_t*)(sm + SMX_A);
    const uint32_t* B32 = (const uint32_t*)(sm + SMX_B);

    float acc[4][7][4];
    #pragma unroll
    for (int mb = 0; mb < 4; mb++)
        #pragma unroll
        for (int nb = 0; nb < 7; nb++)
            #pragma unroll
            for (int q = 0; q < 4; q++) acc[mb][nb][q] = 0.f;

    #pragma unroll 1
    for (int ks = 0; ks < 7; ks++) {
        uint32_t ah[4][4], al[4][4];
        #pragma unroll
        for (int mb = 0; mb < 4; mb++) {
            int w = (wm * 64 + mb * 16 + gid) * ROWW + ks * 8 + tig;
            ah[mb][0] = A32[w];            al[mb][0] = A32[w + 7680];
            ah[mb][1] = A32[w + 8 * ROWW]; al[mb][1] = A32[w + 7680 + 8 * ROWW];
            ah[mb][2] = A32[w + 4];        al[mb][2] = A32[w + 7680 + 4];
            ah[mb][3] = A32[w + 8 * ROWW + 4];
            al[mb][3] = A32[w + 7680 + 8 * ROWW + 4];
        }
        #pragma unroll
        for (int nb = 0; nb < 7; nb++) {
            int w = (wn * 56 + nb * 8 + gid) * ROWW + ks * 8 + tig;
            uint32_t bh0 = B32[w], bh1 = B32[w + 4];
            uint32_t bl0 = B32[w + 13440], bl1 = B32[w + 13440 + 4];
            #pragma unroll
            for (int mb = 0; mb < 4; mb++) {
                mma_fp16(acc[mb][nb], ah[mb], bh0, bh1);
                mma_fp16(acc[mb][nb], ah[mb], bl0, bl1);
                mma_fp16(acc[mb][nb], al[mb], bh0, bh1);
            }
        }
    }

    const float* biasS = (const float*)(sm + SMX_BIAS);
    #pragma unroll
    for (int nb = 0; nb < 7; nb++) {
        int jl = wn * 56 + nb * 8 + tig * 2;
        int j  = n0 + jl;
        if (j < G4) {
            float b0 = biasS[jl], b1 = biasS[jl + 1];
            #pragma unroll
            for (int mb = 0; mb < 4; mb++) {
                int row = m0 + wm * 64 + mb * 16 + gid;
                *(float2*)(g_gx + (size_t)row * G4 + j) =
                    make_float2(acc[mb][nb][0] + b0, acc[mb][nb][1] + b1);
                *(float2*)(g_gx + (size_t)(row + 8) * G4 + j) =
                    make_float2(acc[mb][nb][2] + b0, acc[mb][nb][3] + b1);
            }
        }
    }
}

// ---------------------------------------------------------------------------
// Kernel 2 (FUSED): blocks 0..15 = LSTM (publishes fp16 A every 8 steps);
// blocks 16..147 = persistent GEMM consuming chunks in t-order. LSTM blocks
// fall through into the GEMM when done. GEMM is 1-term fp16 (A hi x B hi).
// ---------------------------------------------------------------------------
#define FS_BIAS 0                      // 192 floats
#define FS_SEG  768
#define FS_A    1024
#define FS_ABUF 30720                  // per buffer: hi only (128 x 240)
#define FS_B    (FS_A + 2 * FS_ABUF)   // 62464 (hi only, 192*240 = 46080)
#define FS_TOT  (FS_B + NT * ROWB)     // 108544
// LSTM smem layout (same buffer, disjoint use): h_s@0, acts@512, h_hist@2176

__device__ __forceinline__ void poll_need(int need) {
    if (threadIdx.x == 0) {
        for (;;) {
            int mn = 0x7fffffff;
            #pragma unroll
            for (int q = 0; q < BATCH; q++) mn = min(mn, ld_acq(&g_prog[q]));
            if (mn >= need) break;
            __nanosleep(256);
        }
    }
    __syncthreads();
}

__global__ __launch_bounds__(416, 1) void fused_kernel(
        const float* __restrict__ W_hh,
        const float* __restrict__ out_b,
        float* __restrict__ out) {
    extern __shared__ char sm[];
    const uint32_t sb = smem_u32(sm);
    const int tid = threadIdx.x;

    if (blockIdx.x < BATCH) {
        // ===================== LSTM producer =====================
        float* h_s    = (float*)sm;            // 100 floats
        float* acts   = (float*)(sm + 512);    // 400 floats
        float* h_hist = (float*)(sm + 2176);   // 8 x 112 floats
        const int j = tid;
        const int b = blockIdx.x;

        unsigned long long w2[50];
        if (j < G4) {
            const unsigned long long* wg =
                (const unsigned long long*)(W_hh + (size_t)j * HID);
            #pragma unroll
            for (int k = 0; k < 50; k++) w2[k] = wg[k];
        }
        if (j < HID) h_s[j] = 0.f;
        float c = 0.f;
        float gcur = (j < G4) ? g_gx[(size_t)b * G4 + j] : 0.f;
        __syncthreads();

        for (int t = 0; t < T_STEPS; t++) {
            float gnext = 0.f;
            if (t + 1 < T_STEPS && j < G4)
                gnext = g_gx[((size_t)(t + 1) * BATCH + b) * G4 + j];

            float a = 0.f;
            if (j < G4) {
                const unsigned long long* h2 = (const unsigned long long*)h_s;
                unsigned long long acc0, acc1;
                asm("mov.b64 %0, {%1, %1};" : "=l"(acc0) : "r"(0));
                asm("mov.b64 %0, {%1, %1};" : "=l"(acc1) : "r"(0));
                #pragma unroll
                for (int k = 0; k < 50; k += 2) {
                    asm("fma.rn.f32x2 %0, %1, %2, %0;"
                        : "+l"(acc0) : "l"(w2[k]), "l"(h2[k]));
                    asm("fma.rn.f32x2 %0, %1, %2, %0;"
                        : "+l"(acc1) : "l"(w2[k + 1]), "l"(h2[k + 1]));
                }
                float s0lo, s0hi, s1lo, s1hi;
                asm("mov.b64 {%0, %1}, %2;" : "=f"(s0lo), "=f"(s0hi) : "l"(acc0));
                asm("mov.b64 {%0, %1}, %2;" : "=f"(s1lo), "=f"(s1hi) : "l"(acc1));
                float d = gcur + (s0lo + s0hi) + (s1lo + s1hi);
                if (j >= 2 * HID && j < 3 * HID) a = tanh_fast(d);
                else                             a = sigf(d);
                acts[j] = a;
            }
            __syncthreads();

            if (j < HID) {
                float ig = acts[j], fg = acts[HID + j];
                float gg = acts[2 * HID + j], og = acts[3 * HID + j];
                c = fg * c + ig * gg;
                float hn = og * tanh_fast(c);
                h_s[j] = hn;
                h_hist[(t & 7) * KP + j] = hn;
            }
            __syncthreads();

            if ((t & 7) == 7) {
                // flush 8 rows as coalesced fp16 (112 units of 8 k, hi only)
                if (tid < 112) {
                    int row = tid / 14, cc = tid % 14;
                    size_t grow = (size_t)(t - 7 + row) * BATCH + b;
                    float v[8];
                    #pragma unroll
                    for (int i = 0; i < 8; i++) {
                        int k = cc * 8 + i;
                        v[i] = (k < HID) ? h_hist[row * KP + k] : 0.f;
                    }
                    uint32_t ph[4];
                    pack8(v, ph);
                    *(uint4*)(gA_hi + grow * KP + cc * 8) =
                        make_uint4(ph[0], ph[1], ph[2], ph[3]);
                }
                __syncthreads();                  // flush stores issued (CTA order)
                if (tid == 0) st_rel(&g_prog[b], t + 1);   // release to gpu scope
            }
            gcur = gnext;
        }
        __syncthreads();
        // fall through: help the GEMM with remaining segments
    }

    // ===================== GEMM consumer (1-term fp16) =====================
    const int wid = tid >> 5, lane = tid & 31;
    const int wm = (wid < 12) ? (wid / 6) : 0;     // 2(M) x 6(N), warps 0..11
    const int wn = (wid < 12) ? (wid % 6) : 0;
    const int gid = lane >> 2, tig = lane & 3;

    const uint32_t a_off = (uint32_t)(wm * 64 * ROWB +
                                      (lane & 15) * ROWB + (lane >> 4) * 16);
    const uint32_t b_base = sb + FS_B +
        (uint32_t)((wn * 32 + ((lane >> 4) & 1) * 8 + (lane & 7)) * ROWB +
                   ((lane >> 3) & 1) * 16);

    for (;;) {
        if (tid == 0) *(int*)(sm + FS_SEG) = atomicAdd(&g_counter, 1);
        __syncthreads();
        const int seg = *(const int*)(sm + FS_SEG);
        if (seg >= NSEG) break;
        const int mch  = seg / NBLK;          // chunk index (t-ordered)
        const int nblk = seg - mch * NBLK;
        const int n0   = nblk * NT;
        const int mt0  = mch * SEG_M;

        // bias + B (do not depend on LSTM progress)
        if (tid < NT) {
            int col = n0 + tid;
            ((float*)(sm + FS_BIAS))[tid] = (col < VOCAB) ? out_b[col] : 0.f;
        }
        for (int e = tid; e < 2688; e += 416) {
            int r = e / 14, cc = e % 14;
            cp16(sb + FS_B + r * ROWB + cc * 16,
                 gW_hi + (size_t)(n0 + r) * KP + cc * 8);
        }
        // wait for tile 0 rows, then load A0
        poll_need((mt0 + 1) * 8);
        {
            const int m0 = mt0 * MT;
            for (int e = tid; e < 1792; e += 416) {
                int r = e / 14, cc = e % 14;
                cp16(sb + FS_A + r * ROWB + cc * 16,
                     gA_hi + (size_t)(m0 + r) * KP + cc * 8);
            }
        }
        asm volatile("cp.async.commit_group;");
        asm volatile("cp.async.wait_group 0;");
        __syncthreads();

        #pragma unroll 1
        for (int it = 0; it < SEG_M; it++) {
            if (it < SEG_M - 1) {   // gate + prefetch next A tile
                poll_need((mt0 + it + 2) * 8);
                const int m1 = (mt0 + it + 1) * MT;
                const uint32_t abase = sb + FS_A + ((it + 1) & 1) * FS_ABUF;
                for (int e = tid; e < 1792; e += 416) {
                    int r = e / 14, cc = e % 14;
                    cp16(abase + r * ROWB + cc * 16,
                         gA_hi + (size_t)(m1 + r) * KP + cc * 8);
                }
                asm volatile("cp.async.commit_group;");
            }

            if (wid < 12) {
                const uint32_t a_cur = sb + FS_A + (it & 1) * FS_ABUF + a_off;

                float acc[4][4][4];
                #pragma unroll
                for (int mb = 0; mb < 4; mb++)
                    #pragma unroll
                    for (int nb = 0; nb < 4; nb++)
                        #pragma unroll
                        for (int q = 0; q < 4; q++) acc[mb][nb][q] = 0.f;

                #pragma unroll
                for (int ks = 0; ks < 7; ks++) {
                    uint32_t ah[4][4], bb[2][4];
                    #pragma unroll
                    for (int mb = 0; mb < 4; mb++)
                        LDSM4(ah[mb], a_cur + mb * 3840 + ks * 32);
                    #pragma unroll
                    for (int p = 0; p < 2; p++)
                        LDSM4(bb[p], b_base + p * 3840 + ks * 32);

                    #pragma unroll
                    for (int p = 0; p < 2; p++) {
                        #pragma unroll
                        for (int mb = 0; mb < 4; mb++) {
                            mma_fp16(acc[mb][2*p],   ah[mb], bb[p][0], bb[p][1]);
                            mma_fp16(acc[mb][2*p+1], ah[mb], bb[p][2], bb[p][3]);
                        }
                    }
                }

                const int m0 = (mt0 + it) * MT;
                const float* biasS = (const float*)(sm + FS_BIAS);
                #pragma unroll
                for (int nb = 0; nb < 4; nb++) {
                    int cl  = wn * 32 + nb * 8 + tig * 2;
                    int col = n0 + cl;
                    if (col < VOCAB) {
                        float b0 = biasS[cl], b1 = biasS[cl + 1];
                        #pragma unroll
                        for (int mb = 0; mb < 4; mb++) {
                            int row = m0 + wm * 64 + mb * 16 + gid;
                            *(float2*)(out + (size_t)row * VOCAB + col) =
                                make_float2(acc[mb][nb][0] + b0,
                                            acc[mb][nb][1] + b1);
                            *(float2*)(out + (size_t)(row + 8) * VOCAB + col) =
                                make_float2(acc[mb][nb][2] + b0,
                                            acc[mb][nb][3] + b1);
                        }
                    }
                }
            }

            if (it < SEG_M - 1) asm volatile("cp.async.wait_group 0;");
            __syncthreads();
        }
    }
}

// ---------------------------------------------------------------------------
// Launch. Inputs: 0 input, 1 emb, 2..5 enc_* (dead), 6 dec_W_ih, 7 dec_W_hh,
// 8 dec_b_ih, 9 dec_b_hh, 10 out_W, 11 out_b.
// ---------------------------------------------------------------------------
extern "C" void kernel_launch(void* const* d_in, const int* in_sizes, int n_in,
                              void* d_out, int out_size) {
    (void)in_sizes; (void)n_in; (void)out_size;
    const int*   input = (const int*)d_in[0];
    const float* emb   = (const float*)d_in[1];
    const float* dWih  = (const float*)d_in[6];
    const float* dWhh  = (const float*)d_in[7];
    const float* dbih  = (const float*)d_in[8];
    const float* dbhh  = (const float*)d_in[9];
    const float* outW  = (const float*)d_in[10];
    const float* outb  = (const float*)d_in[11];
    float* out = (float*)d_out;

    cudaFuncSetAttribute(gx_mma_kernel,
                         cudaFuncAttributeMaxDynamicSharedMemorySize, SMX_TOT);
    cudaFuncSetAttribute(fused_kernel,
                         cudaFuncAttributeMaxDynamicSharedMemorySize, FS_TOT);

    presplit_kernel<<<U_TOT / 256, 256>>>(input, emb, dWih, outW);
    gx_mma_kernel<<<64, 256, SMX_TOT>>>(dbih, dbhh);
    fused_kernel<<<148, 416, FS_TOT>>>(dWhh, outb, out);
}

// round 11
// speedup vs baseline: 1.2192x; 1.0102x over previous
#include <cuda_runtime.h>
#include <cuda_fp16.h>
#include <cstdint>

#define T_STEPS 256
#define BATCH   16
#define HID     100
#define G4      400
#define VOCAB   30522
#define M_ROWS  4096   // T*B
#define KP      112    // K padded to 7 x 16

// Vocab GEMM tiling (fused kernel)
#define MT    128
#define NT    192
#define NBLK  159               // ceil(VOCAB/192)
#define NPAD  (NBLK * NT)       // 30528
#define SEG_M 4                 // m-tiles per segment -> 512-row chunks
#define NCHK  8                 // 4096 / 512
#define NSEG  (NCHK * NBLK)     // 1272
#define ROWB  240               // smem row bytes (112 fp16 = 224, pad to 240)
#define ROWW  60

// gx GEMM tiling
#define GXM   128
#define GXN   224

// ---------------------------------------------------------------------------
// Device scratch
// ---------------------------------------------------------------------------
__device__ float g_gx[(size_t)M_ROWS * G4];
__device__ __align__(16) __half gA_hi[(size_t)M_ROWS * KP];   // A: fp16 hi ONLY
__device__ __align__(16) __half gW_hi[(size_t)NPAD * KP];     // vocab W: hi only
__device__ __align__(16) __half gE_hi[(size_t)M_ROWS * KP];
__device__ __align__(16) __half gE_lo[(size_t)M_ROWS * KP];
__device__ __align__(16) __half gWih_hi[(size_t)448 * KP];
__device__ __align__(16) __half gWih_lo[(size_t)448 * KP];
__device__ int g_counter;
__device__ int g_prog[BATCH];    // lstm steps published, per batch element

// ---------------------------------------------------------------------------
// helpers
// ---------------------------------------------------------------------------
__device__ __forceinline__ uint32_t smem_u32(const void* p) {
    uint32_t a;
    asm("{ .reg .u64 t; cvta.to.shared.u64 t, %1; cvt.u32.u64 %0, t; }"
        : "=r"(a) : "l"(p));
    return a;
}
__device__ __forceinline__ void cp16(uint32_t dst, const void* src) {
    asm volatile("cp.async.ca.shared.global [%0], [%1], 16;" :: "r"(dst), "l"(src));
}
__device__ __forceinline__ void mma_fp16(float* c, const uint32_t* a,
                                         uint32_t b0, uint32_t b1) {
    asm volatile(
        "mma.sync.aligned.m16n8k16.row.col.f32.f16.f16.f32 "
        "{%0,%1,%2,%3},{%4,%5,%6,%7},{%8,%9},{%0,%1,%2,%3};\n"
        : "+f"(c[0]), "+f"(c[1]), "+f"(c[2]), "+f"(c[3])
        : "r"(a[0]), "r"(a[1]), "r"(a[2]), "r"(a[3]), "r"(b0), "r"(b1));
}
#define LDSM4(r, a) \
    asm volatile("ldmatrix.sync.aligned.m8n8.x4.shared.b16 {%0,%1,%2,%3}, [%4];" \
        : "=r"((r)[0]), "=r"((r)[1]), "=r"((r)[2]), "=r"((r)[3]) : "r"(a))

__device__ __forceinline__ void split8(const float* v, uint32_t* ph, uint32_t* pl) {
    #pragma unroll
    for (int j = 0; j < 4; j++) {
        __half h0 = __float2half_rn(v[2*j]);
        __half h1 = __float2half_rn(v[2*j+1]);
        __half l0 = __float2half_rn(v[2*j]   - __half2float(h0));
        __half l1 = __float2half_rn(v[2*j+1] - __half2float(h1));
        ph[j] = (uint32_t)__half_as_ushort(h0) | ((uint32_t)__half_as_ushort(h1) << 16);
        pl[j] = (uint32_t)__half_as_ushort(l0) | ((uint32_t)__half_as_ushort(l1) << 16);
    }
}
__device__ __forceinline__ void pack8(const float* v, uint32_t* ph) {
    #pragma unroll
    for (int j = 0; j < 4; j++) {
        __half h0 = __float2half_rn(v[2*j]);
        __half h1 = __float2half_rn(v[2*j+1]);
        ph[j] = (uint32_t)__half_as_ushort(h0) | ((uint32_t)__half_as_ushort(h1) << 16);
    }
}
__device__ __forceinline__ int ld_acq(const int* p) {
    int v;
    asm volatile("ld.acquire.gpu.global.b32 %0, [%1];" : "=r"(v) : "l"(p) : "memory");
    return v;
}
__device__ __forceinline__ void st_rel(int* p, int v) {
    asm volatile("st.release.gpu.global.b32 [%0], %1;" :: "l"(p), "r"(v) : "memory");
}

// ---------------------------------------------------------------------------
// Kernel 0: presplit + reset counter/progress.  (unchanged)
// ---------------------------------------------------------------------------
#define U_E    (M_ROWS * 14)
#define U_WIH  (448 * 14)
#define U_W    (NPAD * 14)
#define U_TOT  (U_E + U_WIH + U_W)           // 491008 = 1918*256

__global__ __launch_bounds__(256) void presplit_kernel(
        const int* __restrict__ input, const float* __restrict__ emb,
        const float* __restrict__ dec_W_ih, const float* __restrict__ out_W) {
    if (blockIdx.x == 0) {
        if (threadIdx.x < BATCH) g_prog[threadIdx.x] = 0;
        if (threadIdx.x == BATCH) g_counter = 0;
    }
    const int u = blockIdx.x * 256 + threadIdx.x;
    float v[8];
    uint32_t ph[4], pl[4];

    if (u < U_E) {
        int row = u / 14, k0 = (u % 14) * 8;
        const float* src = emb + (size_t)input[row] * HID;
        #pragma unroll
        for (int i = 0; i < 8; i++) {
            int k = k0 + i;
            v[i] = (k < HID) ? src[k] : 0.f;
        }
        split8(v, ph, pl);
        size_t d = (size_t)row * KP + k0;
        *(uint4*)(gE_hi + d) = make_uint4(ph[0], ph[1], ph[2], ph[3]);
        *(uint4*)(gE_lo + d) = make_uint4(pl[0], pl[1], pl[2], pl[3]);
    } else if (u < U_E + U_WIH) {
        int w = u - U_E;
        int row = w / 14, k0 = (w % 14) * 8;
        #pragma unroll
        for (int i = 0; i < 8; i++) {
            int k = k0 + i;
            v[i] = (row < G4 && k < HID) ? dec_W_ih[(size_t)row * HID + k] : 0.f;
        }
        split8(v, ph, pl);
        size_t d = (size_t)row * KP + k0;
        *(uint4*)(gWih_hi + d) = make_uint4(ph[0], ph[1], ph[2], ph[3]);
        *(uint4*)(gWih_lo + d) = make_uint4(pl[0], pl[1], pl[2], pl[3]);
    } else {
        int w = u - U_E - U_WIH;
        int row = w / 14, k0 = (w % 14) * 8;
        #pragma unroll
        for (int i = 0; i < 8; i++) {
            int k = k0 + i;
            v[i] = (row < VOCAB && k < HID) ? out_W[(size_t)row * HID + k] : 0.f;
        }
        pack8(v, ph);
        *(uint4*)(gW_hi + (size_t)row * KP + k0) =
            make_uint4(ph[0], ph[1], ph[2], ph[3]);
    }
}

// ---------------------------------------------------------------------------
// Kernel 1: gx via HMMA (3-term split, precision load-bearing). Grid 64.
// ---------------------------------------------------------------------------
#define SMX_BIAS 0
#define SMX_A    1024
#define SMX_B    (SMX_A + 2 * GXM * ROWB)
#define SMX_TOT  (SMX_B + 2 * GXN * ROWB)    // 169984

__global__ __launch_bounds__(256, 1) void gx_mma_kernel(
        const float* __restrict__ b_ih, const float* __restrict__ b_hh) {
    extern __shared__ char sm[];
    const uint32_t sb = smem_u32(sm);
    const int tid = threadIdx.x;
    const int nblk = blockIdx.x & 1, mt = blockIdx.x >> 1;
    const int m0 = mt * GXM, n0 = nblk * GXN;

    for (int c = tid; c < GXN; c += 256) {
        int j = n0 + c;
        ((float*)(sm + SMX_BIAS))[c] = (j < G4) ? b_ih[j] + b_hh[j] : 0.f;
    }
    for (int e = tid; e < 3584; e += 256) {
        int arr = e >= 1792, r = (e - arr * 1792) / 14, c = e % 14;
        const __half* src = (arr ? gE_lo : gE_hi) + (size_t)(m0 + r) * KP + c * 8;
        cp16(sb + SMX_A + arr * 30720 + r * ROWB + c * 16, src);
    }
    for (int e = tid; e < 6272; e += 256) {
        int arr = e >= 3136, r = (e - arr * 3136) / 14, c = e % 14;
        const __half* src = (arr ? gWih_lo : gWih_hi) + (size_t)(n0 + r) * KP + c * 8;
        cp16(sb + SMX_B + arr * 53760 + r * ROWB + c * 16, src);
    }
    asm volatile("cp.async.commit_group;");
    asm volatile("cp.async.wait_group 0;");
    __syncthreads();

    const int wid = tid >> 5, lane = tid & 31;
    const int wm = wid >> 2, wn = wid & 3;
    const int gid = lane >> 2, tig = lane & 3;
    const uint32_t* A32 = (const uint32_t*)(sm + SMX_A);
    const uint32_t* B32 = (const uint32_t*)(sm + SMX_B);

    float acc[4][7][4];
    #pragma unroll
    for (int mb = 0; mb < 4; mb++)
        #pragma unroll
        for (int nb = 0; nb < 7; nb++)
            #pragma unroll
            for (int q = 0; q < 4; q++) acc[mb][nb][q] = 0.f;

    #pragma unroll 1
    for (int ks = 0; ks < 7; ks++) {
        uint32_t ah[4][4], al[4][4];
        #pragma unroll
        for (int mb = 0; mb < 4; mb++) {
            int w = (wm * 64 + mb * 16 + gid) * ROWW + ks * 8 + tig;
            ah[mb][0] = A32[w];            al[mb][0] = A32[w + 7680];
            ah[mb][1] = A32[w + 8 * ROWW]; al[mb][1] = A32[w + 7680 + 8 * ROWW];
            ah[mb][2] = A32[w + 4];        al[mb][2] = A32[w + 7680 + 4];
            ah[mb][3] = A32[w + 8 * ROWW + 4];
            al[mb][3] = A32[w + 7680 + 8 * ROWW + 4];
        }
        #pragma unroll
        for (int nb = 0; nb < 7; nb++) {
            int w = (wn * 56 + nb * 8 + gid) * ROWW + ks * 8 + tig;
            uint32_t bh0 = B32[w], bh1 = B32[w + 4];
            uint32_t bl0 = B32[w + 13440], bl1 = B32[w + 13440 + 4];
            #pragma unroll
            for (int mb = 0; mb < 4; mb++) {
                mma_fp16(acc[mb][nb], ah[mb], bh0, bh1);
                mma_fp16(acc[mb][nb], ah[mb], bl0, bl1);
                mma_fp16(acc[mb][nb], al[mb], bh0, bh1);
            }
        }
    }

    const float* biasS = (const float*)(sm + SMX_BIAS);
    #pragma unroll
    for (int nb = 0; nb < 7; nb++) {
        int jl = wn * 56 + nb * 8 + tig * 2;
        int j  = n0 + jl;
        if (j < G4) {
            float b0 = biasS[jl], b1 = biasS[jl + 1];
            #pragma unroll
            for (int mb = 0; mb < 4; mb++) {
                int row = m0 + wm * 64 + mb * 16 + gid;
                *(float2*)(g_gx + (size_t)row * G4 + j) =
                    make_float2(acc[mb][nb][0] + b0, acc[mb][nb][1] + b1);
                *(float2*)(g_gx + (size_t)(row + 8) * G4 + j) =
                    make_float2(acc[mb][nb][2] + b0, acc[mb][nb][3] + b1);
            }
        }
    }
}

// ---------------------------------------------------------------------------
// Kernel 2 (FUSED): blocks 0..15 = LSTM (publishes fp16 A every 8 steps);
// blocks 16..147 = persistent GEMM consuming chunks in t-order. LSTM blocks
// fall through into the GEMM when done. GEMM is 1-term fp16 (A hi x B hi).
// LSTM activations: LIBRARY tanhf/expf (R7-proven; __expf variants regress).
// ---------------------------------------------------------------------------
#define FS_BIAS 0                      // 192 floats
#define FS_SEG  768
#define FS_A    1024
#define FS_ABUF 30720                  // per buffer: hi only (128 x 240)
#define FS_B    (FS_A + 2 * FS_ABUF)   // 62464 (hi only, 192*240 = 46080)
#define FS_TOT  (FS_B + NT * ROWB)     // 108544
// LSTM smem layout (same buffer, disjoint use): h_s@0, acts@512, h_hist@2176

__device__ __forceinline__ void poll_need(int need) {
    if (threadIdx.x == 0) {
        for (;;) {
            int mn = 0x7fffffff;
            #pragma unroll
            for (int q = 0; q < BATCH; q++) mn = min(mn, ld_acq(&g_prog[q]));
            if (mn >= need) break;
            __nanosleep(256);
        }
    }
    __syncthreads();
}

__global__ __launch_bounds__(416, 1) void fused_kernel(
        const float* __restrict__ W_hh,
        const float* __restrict__ out_b,
        float* __restrict__ out) {
    extern __shared__ char sm[];
    const uint32_t sb = smem_u32(sm);
    const int tid = threadIdx.x;

    if (blockIdx.x < BATCH) {
        // ===================== LSTM producer =====================
        float* h_s    = (float*)sm;            // 100 floats
        float* acts   = (float*)(sm + 512);    // 400 floats
        float* h_hist = (float*)(sm + 2176);   // 8 x 112 floats
        const int j = tid;
        const int b = blockIdx.x;

        unsigned long long w2[50];
        if (j < G4) {
            const unsigned long long* wg =
                (const unsigned long long*)(W_hh + (size_t)j * HID);
            #pragma unroll
            for (int k = 0; k < 50; k++) w2[k] = wg[k];
        }
        if (j < HID) h_s[j] = 0.f;
        float c = 0.f;
        float gcur = (j < G4) ? g_gx[(size_t)b * G4 + j] : 0.f;
        __syncthreads();

        for (int t = 0; t < T_STEPS; t++) {
            float gnext = 0.f;
            if (t + 1 < T_STEPS && j < G4)
                gnext = g_gx[((size_t)(t + 1) * BATCH + b) * G4 + j];

            float a = 0.f;
            if (j < G4) {
                const unsigned long long* h2 = (const unsigned long long*)h_s;
                unsigned long long acc0, acc1;
                asm("mov.b64 %0, {%1, %1};" : "=l"(acc0) : "r"(0));
                asm("mov.b64 %0, {%1, %1};" : "=l"(acc1) : "r"(0));
                #pragma unroll
                for (int k = 0; k < 50; k += 2) {
                    asm("fma.rn.f32x2 %0, %1, %2, %0;"
                        : "+l"(acc0) : "l"(w2[k]), "l"(h2[k]));
                    asm("fma.rn.f32x2 %0, %1, %2, %0;"
                        : "+l"(acc1) : "l"(w2[k + 1]), "l"(h2[k + 1]));
                }
                float s0lo, s0hi, s1lo, s1hi;
                asm("mov.b64 {%0, %1}, %2;" : "=f"(s0lo), "=f"(s0hi) : "l"(acc0));
                asm("mov.b64 {%0, %1}, %2;" : "=f"(s1lo), "=f"(s1hi) : "l"(acc1));
                float d = gcur + (s0lo + s0hi) + (s1lo + s1hi);
                if (j >= 2 * HID && j < 3 * HID) a = tanhf(d);
                else                             a = 1.f / (1.f + expf(-d));
                acts[j] = a;
            }
            __syncthreads();

            if (j < HID) {
                float ig = acts[j], fg = acts[HID + j];
                float gg = acts[2 * HID + j], og = acts[3 * HID + j];
                c = fg * c + ig * gg;
                float hn = og * tanhf(c);
                h_s[j] = hn;
                h_hist[(t & 7) * KP + j] = hn;
            }
            __syncthreads();

            if ((t & 7) == 7) {
                // flush 8 rows as coalesced fp16 (112 units of 8 k, hi only)
                if (tid < 112) {
                    int row = tid / 14, cc = tid % 14;
                    size_t grow = (size_t)(t - 7 + row) * BATCH + b;
                    float v[8];
                    #pragma unroll
                    for (int i = 0; i < 8; i++) {
                        int k = cc * 8 + i;
                        v[i] = (k < HID) ? h_hist[row * KP + k] : 0.f;
                    }
                    uint32_t ph[4];
                    pack8(v, ph);
                    *(uint4*)(gA_hi + grow * KP + cc * 8) =
                        make_uint4(ph[0], ph[1], ph[2], ph[3]);
                }
                __syncthreads();                  // flush stores issued (CTA order)
                if (tid == 0) st_rel(&g_prog[b], t + 1);   // release to gpu scope
            }
            gcur = gnext;
        }
        __syncthreads();
        // fall through: help the GEMM with remaining segments
    }

    // ===================== GEMM consumer (1-term fp16) =====================
    const int wid = tid >> 5, lane = tid & 31;
    const int wm = (wid < 12) ? (wid / 6) : 0;     // 2(M) x 6(N), warps 0..11
    const int wn = (wid < 12) ? (wid % 6) : 0;
    const int gid = lane >> 2, tig = lane & 3;

    const uint32_t a_off = (uint32_t)(wm * 64 * ROWB +
                                      (lane & 15) * ROWB + (lane >> 4) * 16);
    const uint32_t b_base = sb + FS_B +
        (uint32_t)((wn * 32 + ((lane >> 4) & 1) * 8 + (lane & 7)) * ROWB +
                   ((lane >> 3) & 1) * 16);

    for (;;) {
        if (tid == 0) *(int*)(sm + FS_SEG) = atomicAdd(&g_counter, 1);
        __syncthreads();
        const int seg = *(const int*)(sm + FS_SEG);
        if (seg >= NSEG) break;
        const int mch  = seg / NBLK;          // chunk index (t-ordered)
        const int nblk = seg - mch * NBLK;
        const int n0   = nblk * NT;
        const int mt0  = mch * SEG_M;

        // bias + B (do not depend on LSTM progress)
        if (tid < NT) {
            int col = n0 + tid;
            ((float*)(sm + FS_BIAS))[tid] = (col < VOCAB) ? out_b[col] : 0.f;
        }
        for (int e = tid; e < 2688; e += 416) {
            int r = e / 14, cc = e % 14;
            cp16(sb + FS_B + r * ROWB + cc * 16,
                 gW_hi + (size_t)(n0 + r) * KP + cc * 8);
        }
        // wait for tile 0 rows, then load A0
        poll_need((mt0 + 1) * 8);
        {
            const int m0 = mt0 * MT;
            for (int e = tid; e < 1792; e += 416) {
                int r = e / 14, cc = e % 14;
                cp16(sb + FS_A + r * ROWB + cc * 16,
                     gA_hi + (size_t)(m0 + r) * KP + cc * 8);
            }
        }
        asm volatile("cp.async.commit_group;");
        asm volatile("cp.async.wait_group 0;");
        __syncthreads();

        #pragma unroll 1
        for (int it = 0; it < SEG_M; it++) {
            if (it < SEG_M - 1) {   // gate + prefetch next A tile
                poll_need((mt0 + it + 2) * 8);
                const int m1 = (mt0 + it + 1) * MT;
                const uint32_t abase = sb + FS_A + ((it + 1) & 1) * FS_ABUF;
                for (int e = tid; e < 1792; e += 416) {
                    int r = e / 14, cc = e % 14;
                    cp16(abase + r * ROWB + cc * 16,
                         gA_hi + (size_t)(m1 + r) * KP + cc * 8);
                }
                asm volatile("cp.async.commit_group;");
            }

            if (wid < 12) {
                const uint32_t a_cur = sb + FS_A + (it & 1) * FS_ABUF + a_off;

                float acc[4][4][4];
                #pragma unroll
                for (int mb = 0; mb < 4; mb++)
                    #pragma unroll
                    for (int nb = 0; nb < 4; nb++)
                        #pragma unroll
                        for (int q = 0; q < 4; q++) acc[mb][nb][q] = 0.f;

                #pragma unroll
                for (int ks = 0; ks < 7; ks++) {
                    uint32_t ah[4][4], bb[2][4];
                    #pragma unroll
                    for (int mb = 0; mb < 4; mb++)
                        LDSM4(ah[mb], a_cur + mb * 3840 + ks * 32);
                    #pragma unroll
                    for (int p = 0; p < 2; p++)
                        LDSM4(bb[p], b_base + p * 3840 + ks * 32);

                    #pragma unroll
                    for (int p = 0; p < 2; p++) {
                        #pragma unroll
                        for (int mb = 0; mb < 4; mb++) {
                            mma_fp16(acc[mb][2*p],   ah[mb], bb[p][0], bb[p][1]);
                            mma_fp16(acc[mb][2*p+1], ah[mb], bb[p][2], bb[p][3]);
                        }
                    }
                }

                const int m0 = (mt0 + it) * MT;
                const float* biasS = (const float*)(sm + FS_BIAS);
                #pragma unroll
                for (int nb = 0; nb < 4; nb++) {
                    int cl  = wn * 32 + nb * 8 + tig * 2;
                    int col = n0 + cl;
                    if (col < VOCAB) {
                        float b0 = biasS[cl], b1 = biasS[cl + 1];
                        #pragma unroll
                        for (int mb = 0; mb < 4; mb++) {
                            int row = m0 + wm * 64 + mb * 16 + gid;
                            *(float2*)(out + (size_t)row * VOCAB + col) =
                                make_float2(acc[mb][nb][0] + b0,
                                            acc[mb][nb][1] + b1);
                            *(float2*)(out + (size_t)(row + 8) * VOCAB + col) =
                                make_float2(acc[mb][nb][2] + b0,
                                            acc[mb][nb][3] + b1);
                        }
                    }
                }
            }

            if (it < SEG_M - 1) asm volatile("cp.async.wait_group 0;");
            __syncthreads();
        }
    }
}

// ---------------------------------------------------------------------------
// Launch. Inputs: 0 input, 1 emb, 2..5 enc_* (dead), 6 dec_W_ih, 7 dec_W_hh,
// 8 dec_b_ih, 9 dec_b_hh, 10 out_W, 11 out_b.
// ---------------------------------------------------------------------------
extern "C" void kernel_launch(void* const* d_in, const int* in_sizes, int n_in,
                              void* d_out, int out_size) {
    (void)in_sizes; (void)n_in; (void)out_size;
    const int*   input = (const int*)d_in[0];
    const float* emb   = (const float*)d_in[1];
    const float* dWih  = (const float*)d_in[6];
    const float* dWhh  = (const float*)d_in[7];
    const float* dbih  = (const float*)d_in[8];
    const float* dbhh  = (const float*)d_in[9];
    const float* outW  = (const float*)d_in[10];
    const float* outb  = (const float*)d_in[11];
    float* out = (float*)d_out;

    cudaFuncSetAttribute(gx_mma_kernel,
                         cudaFuncAttributeMaxDynamicSharedMemorySize, SMX_TOT);
    cudaFuncSetAttribute(fused_kernel,
                         cudaFuncAttributeMaxDynamicSharedMemorySize, FS_TOT);

    presplit_kernel<<<U_TOT / 256, 256>>>(input, emb, dWih, outW);
    gx_mma_kernel<<<64, 256, SMX_TOT>>>(dbih, dbhh);
    fused_kernel<<<148, 416, FS_TOT>>>(dWhh, outb, out);
}